// round 6
// baseline (speedup 1.0000x reference)
#include <cuda_runtime.h>
#include <cuda_bf16.h>
#include <cstdint>
#include <cstddef>

// Problem dims (fixed by the dataset)
#define Bz 8
#define Tt 128
#define Ee 30522
#define Hh 1000
#define Sz 64
#define NZ 10000
#define G4H 4000
#define ENZ (Ee + NZ)   // 40522

#define NBLK 125
#define NTH (NBLK * 256)

// ---------------- scratch (static device memory; no allocation) ----------------
#define OFF_PRE    0UL             // [B*T, 4H]   4,096,000
#define OFF_EOUT   4096000UL       // [T,B,H]     1,024,000
#define OFF_ENCT   5120000UL       // [B,H,T]     1,024,000
#define OFF_HBUF   6144000UL       // 2x[B,H]     16,000
#define OFF_CBUF   6160000UL       // 2x[B,H]     16,000
#define OFF_MF     6176000UL       // [H,H]       1,000,000
#define OFF_C0     7176000UL       // [H]+pad     1,024
#define OFF_N1     7177024UL       // [S*B,H]     512,000
#define OFF_EMB0   7689024UL       // [B,H]       8,000
#define OFF_HIST   7697024UL       // [S+1,B,H]   520,000
#define OFF_CD     8217024UL       // 2x[B,H]     16,000
#define OFF_EMB    8233024UL       // [B,H]       8,000
#define OFF_APP    8241024UL       // [B,H]       8,000
#define OFF_CMB    8249024UL       // [B,H]       8,000
#define OFF_PN2    8257024UL       // [S*B,128]   65,536
#define OFF_LOGI   8322560UL       // [B,128]     1,024
#define OFF_PARTK  8323584UL       // split-K partials (8M floats)
#define SCRATCH_FLOATS 16323584UL

__device__ float g_scratch[SCRATCH_FLOATS];

// grid-barrier state (zero-initialized; g_cnt always returns to 0)
__device__ unsigned g_cnt = 0;
__device__ unsigned g_gen = 0;

// ---------------- helpers ----------------
__device__ __forceinline__ float wred(float v) {
#pragma unroll
    for (int o = 16; o; o >>= 1) v += __shfl_xor_sync(0xffffffffu, v, o);
    return v;
}
__device__ __forceinline__ float sg(float x) { return 1.f / (1.f + expf(-x)); }

// software grid barrier; REQUIRES all nb blocks resident (nb <= 148, 1 CTA/SM)
__device__ __forceinline__ void gridbar(int nb) {
    __syncthreads();
    if (threadIdx.x == 0) {
        __threadfence();
        volatile unsigned* vgen = &g_gen;
        unsigned g = *vgen;
        if (atomicAdd(&g_cnt, 1u) == (unsigned)(nb - 1)) {
            g_cnt = 0;
            __threadfence();
            *vgen = g + 1;
        } else {
            while (*vgen == g) { }
            __threadfence();
        }
    }
    __syncthreads();
}

__device__ __forceinline__ uint32_t smem_u32(const void* p) {
    uint32_t r;
    asm("{ .reg .u64 t; cvta.to.shared.u64 t, %1; cvt.u32.u64 %0, t; }"
        : "=r"(r) : "l"(p));
    return r;
}
__device__ __forceinline__ void ldsm4(uint32_t& r0, uint32_t& r1, uint32_t& r2, uint32_t& r3,
                                      uint32_t addr) {
    asm volatile("ldmatrix.sync.aligned.m8n8.x4.shared.b16 {%0,%1,%2,%3}, [%4];"
                 : "=r"(r0), "=r"(r1), "=r"(r2), "=r"(r3) : "r"(addr));
}
__device__ __forceinline__ void mma16816(float* c, uint32_t a0, uint32_t a1, uint32_t a2,
                                         uint32_t a3, uint32_t b0, uint32_t b1) {
    asm volatile(
        "mma.sync.aligned.m16n8k16.row.col.f32.bf16.bf16.f32 "
        "{%0,%1,%2,%3},{%4,%5,%6,%7},{%8,%9},{%0,%1,%2,%3};"
        : "+f"(c[0]), "+f"(c[1]), "+f"(c[2]), "+f"(c[3])
        : "r"(a0), "r"(a1), "r"(a2), "r"(a3), "r"(b0), "r"(b1));
}

__global__ void reduceK(const float* __restrict__ part, size_t zstride, int nz,
                        float* __restrict__ C, int n,
                        const float* __restrict__ bias, int ncols) {
    int i = blockIdx.x * blockDim.x + threadIdx.x;
    if (i >= n) return;
    float s = 0.f;
    for (int z = 0; z < nz; z++) s += part[(size_t)z * zstride + i];
    if (bias) s += bias[i % ncols];
    C[i] = s;
}

// ---------------- split-bf16 tensor-core GEMM (unchanged) ----------------
#define LDT 24

template <bool BT>
__global__ __launch_bounds__(256)
void gemm_bf16s(const float* __restrict__ A, long lda,
                const float* __restrict__ B, long ldb,
                float* __restrict__ C, long ldc, size_t zstride,
                int M, int N, int K, int kchunk,
                const float* __restrict__ bias1, const float* __restrict__ bias2)
{
    __shared__ __align__(16) __nv_bfloat16 sm[2][4][128 * LDT]; // [buf][Ah,Al,Bh,Bl]
    const int tid = threadIdx.x;
    const int m0 = blockIdx.y * 128, n0 = blockIdx.x * 128;
    const int kb0 = blockIdx.z * kchunk;
    const int ke = min(K, kb0 + kchunk);
    C += (size_t)blockIdx.z * zstride;

    float acc[2][8][4];
#pragma unroll
    for (int i = 0; i < 2; i++)
#pragma unroll
        for (int j = 0; j < 8; j++)
#pragma unroll
            for (int q = 0; q < 4; q++) acc[i][j][q] = 0.f;

    const int ka = tid & 15, ra = tid >> 4;
    const int nn = tid & 127, k2 = tid >> 7;

    auto gload = [&](int kt, float* av, float* bv) {
#pragma unroll
        for (int i = 0; i < 8; i++) {
            int r = ra + 16 * i;
            int gm = m0 + r, gk = kt + ka;
            av[i] = (gm < M && gk < ke) ? A[(size_t)gm * lda + gk] : 0.f;
        }
        if (BT) {
#pragma unroll
            for (int i = 0; i < 8; i++) {
                int r = ra + 16 * i;
                int gn = n0 + r, gk = kt + ka;
                bv[i] = (gn < N && gk < ke) ? B[(size_t)gn * ldb + gk] : 0.f;
            }
        } else {
#pragma unroll
            for (int i = 0; i < 8; i++) {
                int kk = k2 + 2 * i;
                int gk = kt + kk, gn = n0 + nn;
                bv[i] = (gn < N && gk < ke) ? B[(size_t)gk * ldb + gn] : 0.f;
            }
        }
    };
    auto gstore = [&](int buf, const float* av, const float* bv) {
#pragma unroll
        for (int i = 0; i < 8; i++) {
            int r = ra + 16 * i;
            float v = av[i];
            __nv_bfloat16 hi = __float2bfloat16(v);
            sm[buf][0][r * LDT + ka] = hi;
            sm[buf][1][r * LDT + ka] = __float2bfloat16(v - __bfloat162float(hi));
        }
        if (BT) {
#pragma unroll
            for (int i = 0; i < 8; i++) {
                int r = ra + 16 * i;
                float v = bv[i];
                __nv_bfloat16 hi = __float2bfloat16(v);
                sm[buf][2][r * LDT + ka] = hi;
                sm[buf][3][r * LDT + ka] = __float2bfloat16(v - __bfloat162float(hi));
            }
        } else {
#pragma unroll
            for (int i = 0; i < 8; i++) {
                int kk = k2 + 2 * i;
                float v = bv[i];
                __nv_bfloat16 hi = __float2bfloat16(v);
                sm[buf][2][nn * LDT + kk] = hi;
                sm[buf][3][nn * LDT + kk] = __float2bfloat16(v - __bfloat162float(hi));
            }
        }
    };

    const int lane = tid & 31, w = tid >> 5;
    const int wm = w & 3, wn = w >> 2;
    const int arow = wm * 32 + (lane & 15);
    const int akb = (lane >> 4) * 8;
    const int brow = wn * 64 + (lane & 7) + ((lane >> 4) << 3);
    const int bkb = ((lane >> 3) & 1) * 8;

    const int nk = (ke > kb0) ? (ke - kb0 + 15) / 16 : 0;
    float av[8], bv[8];
    if (nk > 0) {
        gload(kb0, av, bv);
        gstore(0, av, bv);
    }
    __syncthreads();

    for (int it = 0; it < nk; it++) {
        const int buf = it & 1;
        if (it + 1 < nk) gload(kb0 + 16 * (it + 1), av, bv);

        uint32_t ah[2][4], al[2][4], bh[8][2], bl[8][2];
#pragma unroll
        for (int ti = 0; ti < 2; ti++) {
            ldsm4(ah[ti][0], ah[ti][1], ah[ti][2], ah[ti][3],
                  smem_u32(&sm[buf][0][(arow + 16 * ti) * LDT + akb]));
            ldsm4(al[ti][0], al[ti][1], al[ti][2], al[ti][3],
                  smem_u32(&sm[buf][1][(arow + 16 * ti) * LDT + akb]));
        }
#pragma unroll
        for (int tp = 0; tp < 4; tp++) {
            uint32_t r0, r1, r2, r3;
            ldsm4(r0, r1, r2, r3, smem_u32(&sm[buf][2][(brow + 16 * tp) * LDT + bkb]));
            bh[2 * tp][0] = r0; bh[2 * tp][1] = r1;
            bh[2 * tp + 1][0] = r2; bh[2 * tp + 1][1] = r3;
            ldsm4(r0, r1, r2, r3, smem_u32(&sm[buf][3][(brow + 16 * tp) * LDT + bkb]));
            bl[2 * tp][0] = r0; bl[2 * tp][1] = r1;
            bl[2 * tp + 1][0] = r2; bl[2 * tp + 1][1] = r3;
        }
#pragma unroll
        for (int ti = 0; ti < 2; ti++)
#pragma unroll
            for (int tj = 0; tj < 8; tj++) {
                mma16816(acc[ti][tj], ah[ti][0], ah[ti][1], ah[ti][2], ah[ti][3],
                         bh[tj][0], bh[tj][1]);
                mma16816(acc[ti][tj], ah[ti][0], ah[ti][1], ah[ti][2], ah[ti][3],
                         bl[tj][0], bl[tj][1]);
                mma16816(acc[ti][tj], al[ti][0], al[ti][1], al[ti][2], al[ti][3],
                         bh[tj][0], bh[tj][1]);
            }
        if (it + 1 < nk) gstore(buf ^ 1, av, bv);
        __syncthreads();
    }

    const int erow = m0 + wm * 32 + (lane >> 2);
    const int ecol = n0 + wn * 64 + 2 * (lane & 3);
#pragma unroll
    for (int ti = 0; ti < 2; ti++)
#pragma unroll
        for (int tj = 0; tj < 8; tj++) {
            int m = erow + 16 * ti, n = ecol + 8 * tj;
#pragma unroll
            for (int q = 0; q < 4; q++) {
                int mm = m + (q >= 2 ? 8 : 0);
                int nnq = n + (q & 1);
                if (mm < M && nnq < N) {
                    float v = acc[ti][tj][q];
                    if (bias1) v += bias1[nnq];
                    if (bias2) v += bias2[nnq];
                    C[(size_t)mm * ldc + nnq] = v;
                }
            }
        }
}

// ---------------- emb0 + c0 (9 dot-rows vs embA, smem-staged) ----------------
__global__ __launch_bounds__(256)
void emb0_c0(const float* __restrict__ embA, const float* __restrict__ init_dec,
             const float* __restrict__ out_b, float* __restrict__ emb0,
             float* __restrict__ c0)
{
    __shared__ float sx[9][1024];
    const int tid = threadIdx.x, lane = tid & 31, w = tid >> 5;
    const int n = blockIdx.x * 8 + w;
    float acc[9];
#pragma unroll
    for (int r = 0; r < 9; r++) acc[r] = 0.f;
    for (int kb = 0; kb < Ee; kb += 1024) {
        int len = min(1024, Ee - kb);
        for (int idx = tid; idx < 9 * 1024; idx += 256) {
            int r = idx >> 10, c = idx & 1023;
            float v = 0.f;
            if (c < len) v = (r < 8) ? init_dec[(size_t)r * Ee + kb + c] : out_b[kb + c];
            sx[r][c] = v;
        }
        __syncthreads();
        const float* ar = embA + (size_t)n * ENZ + kb;
        for (int k = lane; k < len; k += 32) {
            float a = ar[k];
#pragma unroll
            for (int r = 0; r < 9; r++) acc[r] += a * sx[r][k];
        }
        __syncthreads();
    }
#pragma unroll
    for (int r = 0; r < 9; r++) acc[r] = wred(acc[r]);
    if (lane < 8) emb0[lane * Hh + n] = acc[lane];
    else if (lane == 8) c0[n] = acc[8];
}

// ---------------- persistent encoder: all 128 LSTM steps in one launch ----------------
__global__ __launch_bounds__(256)
void enc_persist(const float* __restrict__ Whh, const float* __restrict__ pre,
                 float* __restrict__ hbuf, float* __restrict__ cbuf,
                 float* __restrict__ eout, float* __restrict__ hist,
                 float* __restrict__ cd)
{
    const int w = blockIdx.x * 8 + (threadIdx.x >> 5);  // 0..999 == h index
    const int lane = threadIdx.x & 31;
    const int gtid = blockIdx.x * 256 + threadIdx.x;
    const int h = w;

    // zero both h/c buffers
    for (int i = gtid; i < 2 * Bz * Hh; i += NTH) { hbuf[i] = 0.f; cbuf[i] = 0.f; }
    gridbar(NBLK);

    for (int t = 0; t < Tt; t++) {
        const float* hp = hbuf + (t & 1) * (Bz * Hh);
        const float* cp = cbuf + (t & 1) * (Bz * Hh);
        float* hn = hbuf + ((t + 1) & 1) * (Bz * Hh);
        float* cn = cbuf + ((t + 1) & 1) * (Bz * Hh);
        const float* pre_t = pre + (size_t)t * G4H;
        float* eo = eout + (size_t)t * (Bz * Hh);

        float acc[4][8];
#pragma unroll
        for (int g = 0; g < 4; g++)
#pragma unroll
            for (int b = 0; b < 8; b++) acc[g][b] = 0.f;

        for (int k = lane; k < Hh; k += 32) {
            float hv[8];
#pragma unroll
            for (int b = 0; b < 8; b++) hv[b] = hp[b * Hh + k];
#pragma unroll
            for (int g = 0; g < 4; g++) {
                float wv = Whh[((size_t)(g * Hh + h)) * Hh + k];
#pragma unroll
                for (int b = 0; b < 8; b++) acc[g][b] += wv * hv[b];
            }
        }
#pragma unroll
        for (int g = 0; g < 4; g++)
#pragma unroll
            for (int b = 0; b < 8; b++) acc[g][b] = wred(acc[g][b]);

        if (lane < 8) {
            int b = lane;
            const float* prb = pre_t + (size_t)b * (Tt * G4H);
            float gi = prb[0 * Hh + h] + acc[0][b];
            float gf = prb[1 * Hh + h] + acc[1][b];
            float gg = prb[2 * Hh + h] + acc[2][b];
            float go = prb[3 * Hh + h] + acc[3][b];
            float iv = sg(gi), fv = sg(gf), gv = tanhf(gg), ov = sg(go);
            float c = fv * cp[b * Hh + h] + iv * gv;
            float hv = ov * tanhf(c);
            cn[b * Hh + h] = c;
            hn[b * Hh + h] = hv;
            eo[b * Hh + h] = hv;
        }
        gridbar(NBLK);
    }
    // after 128 steps, final state is in slot 0
    for (int i = gtid; i < Bz * Hh; i += NTH) { hist[i] = hbuf[i]; cd[i] = cbuf[i]; }
}

// ---------------- transpose eout [T,B,H] -> enc_t [B,H,T] ----------------
__global__ void transpose_enc(const float* __restrict__ eout, float* __restrict__ enc_t)
{
    __shared__ float tile[32][33];
    int b = blockIdx.z;
    int t0 = blockIdx.x * 32, h0 = blockIdx.y * 32;
    int tx = threadIdx.x, ty = threadIdx.y;  // 32 x 8
#pragma unroll
    for (int i = 0; i < 4; i++) {
        int t = t0 + ty + i * 8, h = h0 + tx;
        tile[ty + i * 8][tx] = (h < Hh) ? eout[((size_t)t * Bz + b) * Hh + h] : 0.f;
    }
    __syncthreads();
#pragma unroll
    for (int i = 0; i < 4; i++) {
        int h = h0 + ty + i * 8, t = t0 + tx;
        if (h < Hh) enc_t[((size_t)b * Hh + h) * Tt + t] = tile[tx][ty + i * 8];
    }
}

// ---------------- persistent decoder: all 64 steps, 5 phases each ----------------
__global__ __launch_bounds__(256)
void dec_persist(const float* __restrict__ Mf, const float* __restrict__ c0,
                 const float* __restrict__ N1, const float* __restrict__ emb0,
                 const float* __restrict__ PN2, const float* __restrict__ attn_W,
                 const float* __restrict__ enc_t,
                 const float* __restrict__ comb_W, const float* __restrict__ comb_b,
                 const float* __restrict__ Wih, const float* __restrict__ Whh,
                 const float* __restrict__ bih, const float* __restrict__ bhh,
                 float* __restrict__ hist, float* __restrict__ cd,
                 float* __restrict__ embb, float* __restrict__ appb,
                 float* __restrict__ cmbb, float* __restrict__ logi)
{
    const int w = blockIdx.x * 8 + (threadIdx.x >> 5);  // 0..999
    const int lane = threadIdx.x & 31;
    const int gtid = blockIdx.x * 256 + threadIdx.x;

    for (int s = 0; s < Sz; s++) {
        const float* hs = hist + (size_t)s * (Bz * Hh);

        // ---- phase 1: emb ----
        if (s == 0) {
            for (int i = gtid; i < Bz * Hh; i += NTH) embb[i] = emb0[i] + N1[i];
        } else {
            const int h1 = w;
            const float* n1s = N1 + (size_t)s * (Bz * Hh);
            float acc[8];
#pragma unroll
            for (int b = 0; b < 8; b++) acc[b] = 0.f;
            const float* mrow = Mf + (size_t)h1 * Hh;
            for (int k = lane; k < Hh; k += 32) {
                float mv = mrow[k];
#pragma unroll
                for (int b = 0; b < 8; b++) acc[b] += mv * hs[b * Hh + k];
            }
#pragma unroll
            for (int b = 0; b < 8; b++) acc[b] = wred(acc[b]);
            if (lane < 8) {
                int b = lane;
                embb[b * Hh + h1] = acc[b] + c0[h1] + n1s[b * Hh + h1];
            }
        }
        gridbar(NBLK);

        // ---- phase 2: logits ----
        {
            const float* pn2s = PN2 + (size_t)s * (Bz * Tt);
            for (int gw = w; gw < Bz * Tt; gw += 1000) {
                int b = gw >> 7, t = gw & 127;
                const float* wr = attn_W + (size_t)t * (3 * Hh);
                const float* eb = embb + b * Hh;
                const float* hb = hs + b * Hh;
                float sd = 0.f;
                for (int k = lane; k < Hh; k += 32)
                    sd += eb[k] * wr[k] + hb[k] * wr[Hh + k];
                sd = wred(sd);
                if (lane == 0) logi[b * Tt + t] = sd + pn2s[b * Tt + t];
            }
        }
        gridbar(NBLK);

        // ---- phase 3: softmax (per-warp, in registers) + applied ----
        {
            int b = w & 7;
            float v0 = logi[b * Tt + lane];
            float v1 = logi[b * Tt + 32 + lane];
            float v2 = logi[b * Tt + 64 + lane];
            float v3 = logi[b * Tt + 96 + lane];
            float mx = fmaxf(fmaxf(v0, v1), fmaxf(v2, v3));
#pragma unroll
            for (int o = 16; o; o >>= 1)
                mx = fmaxf(mx, __shfl_xor_sync(0xffffffffu, mx, o));
            float e0 = expf(v0 - mx), e1 = expf(v1 - mx),
                  e2 = expf(v2 - mx), e3 = expf(v3 - mx);
            float inv = 1.f / wred(e0 + e1 + e2 + e3);
            e0 *= inv; e1 *= inv; e2 *= inv; e3 *= inv;
            int hb0 = w >> 3;  // 0..124
#pragma unroll
            for (int it = 0; it < 8; it++) {
                int h = hb0 + 125 * it;
                const float* e = enc_t + ((size_t)b * Hh + h) * Tt;
                float sd = e0 * e[lane] + e1 * e[lane + 32] +
                           e2 * e[lane + 64] + e3 * e[lane + 96];
                sd = wred(sd);
                if (lane == 0) appb[b * Hh + h] = sd;
            }
        }
        gridbar(NBLK);

        // ---- phase 4: combine + relu ----
        {
            const int h1 = w;
            float acc[8];
#pragma unroll
            for (int b = 0; b < 8; b++) acc[b] = 0.f;
            const float* wrow = comb_W + (size_t)h1 * (2 * Hh);
            for (int k = lane; k < 2 * Hh; k += 32) {
                float wv = wrow[k];
                const float* src = (k < Hh) ? embb : appb;
                int kk = (k < Hh) ? k : k - Hh;
#pragma unroll
                for (int b = 0; b < 8; b++) acc[b] += wv * src[b * Hh + kk];
            }
#pragma unroll
            for (int b = 0; b < 8; b++) acc[b] = wred(acc[b]);
            if (lane < 8) {
                int b = lane;
                cmbb[b * Hh + h1] = fmaxf(acc[b] + comb_b[h1], 0.f);
            }
        }
        gridbar(NBLK);

        // ---- phase 5: decoder LSTM ----
        {
            const int h = w;
            const float* cp = cd + (s & 1) * (Bz * Hh);
            float* cn = cd + ((s + 1) & 1) * (Bz * Hh);
            float* hn = hist + (size_t)(s + 1) * (Bz * Hh);
            float acc[4][8];
#pragma unroll
            for (int g = 0; g < 4; g++)
#pragma unroll
                for (int b = 0; b < 8; b++) acc[g][b] = 0.f;

            for (int k = lane; k < Hh; k += 32) {
                float xv[8], hv[8];
#pragma unroll
                for (int b = 0; b < 8; b++) {
                    xv[b] = cmbb[b * Hh + k];
                    hv[b] = hs[b * Hh + k];
                }
#pragma unroll
                for (int g = 0; g < 4; g++) {
                    float wi = Wih[((size_t)(g * Hh + h)) * Hh + k];
                    float wh = Whh[((size_t)(g * Hh + h)) * Hh + k];
#pragma unroll
                    for (int b = 0; b < 8; b++) acc[g][b] += wi * xv[b] + wh * hv[b];
                }
            }
#pragma unroll
            for (int g = 0; g < 4; g++)
#pragma unroll
                for (int b = 0; b < 8; b++) acc[g][b] = wred(acc[g][b]);

            if (lane < 8) {
                int b = lane;
                float gi = acc[0][b] + bih[0 * Hh + h] + bhh[0 * Hh + h];
                float gf = acc[1][b] + bih[1 * Hh + h] + bhh[1 * Hh + h];
                float gg = acc[2][b] + bih[2 * Hh + h] + bhh[2 * Hh + h];
                float go = acc[3][b] + bih[3 * Hh + h] + bhh[3 * Hh + h];
                float iv = sg(gi), fv = sg(gf), gv = tanhf(gg), ov = sg(go);
                float c = fv * cp[b * Hh + h] + iv * gv;
                cn[b * Hh + h] = c;
                hn[b * Hh + h] = ov * tanhf(c);
            }
        }
        gridbar(NBLK);
    }
}

// ---------------- launcher ----------------
extern "C" void kernel_launch(void* const* d_in, const int* in_sizes, int n_in,
                              void* d_out, int out_size)
{
    int p = 0;
    const float* input    = (const float*)d_in[p++];
    if (in_sizes[p] == 1) p++;   // target_size scalar
    const float* noise1   = (const float*)d_in[p++];
    const float* noise2   = (const float*)d_in[p++];
    const float* init_dec = (const float*)d_in[p++];
    const float* enc_Wih  = (const float*)d_in[p++];
    const float* enc_Whh  = (const float*)d_in[p++];
    const float* enc_bih  = (const float*)d_in[p++];
    const float* enc_bhh  = (const float*)d_in[p++];
    const float* dec_Wih  = (const float*)d_in[p++];
    const float* dec_Whh  = (const float*)d_in[p++];
    const float* dec_bih  = (const float*)d_in[p++];
    const float* dec_bhh  = (const float*)d_in[p++];
    const float* emb_W    = (const float*)d_in[p++];
    const float* emb_b    = (const float*)d_in[p++];
    const float* attn_W   = (const float*)d_in[p++];
    const float* attn_b   = (const float*)d_in[p++];
    const float* comb_W   = (const float*)d_in[p++];
    const float* comb_b   = (const float*)d_in[p++];
    const float* out_W    = (const float*)d_in[p++];
    const float* out_b    = (const float*)d_in[p++];
    float* out = (float*)d_out;

    float* base = nullptr;
    cudaGetSymbolAddress((void**)&base, g_scratch);
    float* pre   = base + OFF_PRE;
    float* eout  = base + OFF_EOUT;
    float* enc_t = base + OFF_ENCT;
    float* hbuf  = base + OFF_HBUF;
    float* cbuf  = base + OFF_CBUF;
    float* Mf    = base + OFF_MF;
    float* c0    = base + OFF_C0;
    float* N1    = base + OFF_N1;
    float* emb0  = base + OFF_EMB0;
    float* hist  = base + OFF_HIST;
    float* cd    = base + OFF_CD;
    float* embb  = base + OFF_EMB;
    float* appb  = base + OFF_APP;
    float* cmbb  = base + OFF_CMB;
    float* PN2   = base + OFF_PN2;
    float* logi  = base + OFF_LOGI;
    float* partK = base + OFF_PARTK;

    // G1: pre-gates [B*T,4H] = input @ enc_Wih^T (+bih+bhh)
    gemm_bf16s<true><<<dim3(32, 8, 1), 256>>>(input, Ee, enc_Wih, Ee,
                                              pre, G4H, 0,
                                              Bz * Tt, G4H, Ee, Ee,
                                              enc_bih, enc_bhh);
    // G2 (split-K 8): Mf = embA @ out_W  [1000,1000]
    gemm_bf16s<false><<<dim3(8, 8, 8), 256>>>(emb_W, ENZ, out_W, Hh,
                                              partK, Hh, (size_t)Hh * Hh,
                                              Hh, Hh, Ee, 3824,
                                              nullptr, nullptr);
    reduceK<<<(Hh * Hh + 255) / 256, 256>>>(partK, (size_t)Hh * Hh, 8, Mf, Hh * Hh,
                                            nullptr, 1);
    // G3 (split-K 4): N1 = noise1 @ embNZ^T + emb_b  [512,1000]
    gemm_bf16s<true><<<dim3(8, 4, 4), 256>>>(noise1, NZ, emb_W + Ee, ENZ,
                                             partK, Hh, (size_t)Sz * Bz * Hh,
                                             Sz * Bz, Hh, NZ, 2512,
                                             nullptr, nullptr);
    reduceK<<<(Sz * Bz * Hh + 255) / 256, 256>>>(partK, (size_t)Sz * Bz * Hh, 4,
                                                 N1, Sz * Bz * Hh, emb_b, Hh);
    // PN2 = noise2 @ W3^T + attn_b  [512,128]
    gemm_bf16s<true><<<dim3(1, 4, 1), 256>>>(noise2, Hh, attn_W + 2 * Hh, 3 * Hh,
                                             PN2, Tt, 0,
                                             Sz * Bz, Tt, Hh, Hh,
                                             attn_b, nullptr);
    // emb0 + c0
    emb0_c0<<<125, 256>>>(emb_W, init_dec, out_b, emb0, c0);

    // persistent encoder (all 128 steps; zero-init + final copies folded in)
    enc_persist<<<NBLK, 256>>>(enc_Whh, pre, hbuf, cbuf, eout, hist, cd);

    transpose_enc<<<dim3(4, 32, 8), dim3(32, 8)>>>(eout, enc_t);

    // persistent decoder (all 64 steps)
    dec_persist<<<NBLK, 256>>>(Mf, c0, N1, emb0, PN2, attn_W, enc_t,
                               comb_W, comb_b, dec_Wih, dec_Whh, dec_bih, dec_bhh,
                               hist, cd, embb, appb, cmbb, logi);

    // summary = hist[1..S] @ out_W^T + out_b  -> [512, 30522]
    gemm_bf16s<true><<<dim3(239, 4, 1), 256>>>(hist + Bz * Hh, Hh, out_W, Hh,
                                               out, Ee, 0,
                                               Sz * Bz, Ee, Hh, Hh,
                                               out_b, nullptr);
}

// round 8
// speedup vs baseline: 1.2472x; 1.2472x over previous
#include <cuda_runtime.h>
#include <cuda_bf16.h>
#include <cstdint>
#include <cstddef>

// Problem dims (fixed by the dataset)
#define Bz 8
#define Tt 128
#define Ee 30522
#define Hh 1000
#define Sz 64
#define NZ 10000
#define G4H 4000
#define ENZ (Ee + NZ)   // 40522

// ---------------- scratch (static device memory; no allocation) ----------------
#define OFF_PRE    0UL             // [B*T, 4H]   4,096,000
#define OFF_EOUT   4096000UL       // [T,B,H]     1,024,000
#define OFF_ENCT   5120000UL       // [B,H,T]     1,024,000
#define OFF_HBUF   6144000UL       // 2x[B,H]     16,000
#define OFF_CBUF   6160000UL       // 2x[B,H]     16,000
#define OFF_MF     6176000UL       // [H,H]       1,000,000
#define OFF_C0     7176000UL       // [H]+pad     1,024
#define OFF_N1     7177024UL       // [S*B,H]     512,000
#define OFF_EMB0   7689024UL       // [B,H]       8,000
#define OFF_HIST   7697024UL       // [S+1,B,H]   520,000
#define OFF_CD     8217024UL       // 2x[B,H]     16,000
#define OFF_EMB    8233024UL       // [B,H]       8,000
#define OFF_APP    8241024UL       // [B,H]       8,000
#define OFF_CMB    8249024UL       // [B,H]       8,000
#define OFF_PN2    8257024UL       // [S*B,128]   65,536
#define OFF_LOGI   8322560UL       // [B,128]     1,024
#define OFF_PARTK  8323584UL       // split-K partials (8M floats)
#define SCRATCH_FLOATS 16323584UL

__device__ float g_scratch[SCRATCH_FLOATS];

// ---------------- helpers ----------------
__device__ __forceinline__ float wred(float v) {
#pragma unroll
    for (int o = 16; o; o >>= 1) v += __shfl_xor_sync(0xffffffffu, v, o);
    return v;
}
__device__ __forceinline__ float sg(float x) { return 1.f / (1.f + expf(-x)); }

__device__ __forceinline__ uint32_t smem_u32(const void* p) {
    uint32_t r;
    asm("{ .reg .u64 t; cvta.to.shared.u64 t, %1; cvt.u32.u64 %0, t; }"
        : "=r"(r) : "l"(p));
    return r;
}
__device__ __forceinline__ void ldsm4(uint32_t& r0, uint32_t& r1, uint32_t& r2, uint32_t& r3,
                                      uint32_t addr) {
    asm volatile("ldmatrix.sync.aligned.m8n8.x4.shared.b16 {%0,%1,%2,%3}, [%4];"
                 : "=r"(r0), "=r"(r1), "=r"(r2), "=r"(r3) : "r"(addr));
}
__device__ __forceinline__ void mma16816(float* c, uint32_t a0, uint32_t a1, uint32_t a2,
                                         uint32_t a3, uint32_t b0, uint32_t b1) {
    asm volatile(
        "mma.sync.aligned.m16n8k16.row.col.f32.bf16.bf16.f32 "
        "{%0,%1,%2,%3},{%4,%5,%6,%7},{%8,%9},{%0,%1,%2,%3};"
        : "+f"(c[0]), "+f"(c[1]), "+f"(c[2]), "+f"(c[3])
        : "r"(a0), "r"(a1), "r"(a2), "r"(a3), "r"(b0), "r"(b1));
}

__global__ void zero_kernel(float* p, int n) {
    int i = blockIdx.x * blockDim.x + threadIdx.x;
    if (i < n) p[i] = 0.f;
}
__global__ void copy_kernel(float* dst, const float* src, int n) {
    int i = blockIdx.x * blockDim.x + threadIdx.x;
    if (i < n) dst[i] = src[i];
}
__global__ void add2_kernel(float* dst, const float* a, const float* b, int n) {
    int i = blockIdx.x * blockDim.x + threadIdx.x;
    if (i < n) dst[i] = a[i] + b[i];
}
__global__ void reduceK(const float* __restrict__ part, size_t zstride, int nz,
                        float* __restrict__ C, int n,
                        const float* __restrict__ bias, int ncols) {
    int i = blockIdx.x * blockDim.x + threadIdx.x;
    if (i >= n) return;
    float s = 0.f;
    for (int z = 0; z < nz; z++) s += part[(size_t)z * zstride + i];
    if (bias) s += bias[i % ncols];
    C[i] = s;
}

// ---------------- split-bf16 tensor-core GEMM ----------------
// C[M,N] = A[M,K] * op(B)  (+bias1+bias2)
// BT=true : B is [N,K] row-major (C = A @ B^T)
// BT=false: B is [K,N] row-major (C = A @ B)
// fp32 value = hi(bf16) + lo(bf16); product uses hi*hi + hi*lo + lo*hi.
// SMEM: XOR-swizzled 32B rows (no pad): element e (0..15) of row r lives at
// byte  r*32 + (((e>>3) ^ ((r>>2)&1))<<4) + (e&7)*2.
// Verified conflict-free for every ldsm 8-row phase and 16B-aligned.
#define MATB (128 * 16)  // bf16 elements per matrix buffer (4KB)

__device__ __forceinline__ int swoff(int r, int e) {
    return r * 32 + ((((e >> 3) ^ (r >> 2)) & 1) << 4) + (e & 7) * 2;
}

template <bool BT>
__global__ __launch_bounds__(256, 2)
void gemm_bf16s(const float* __restrict__ A, long lda,
                const float* __restrict__ B, long ldb,
                float* __restrict__ C, long ldc, size_t zstride,
                int M, int N, int K, int kchunk,
                const float* __restrict__ bias1, const float* __restrict__ bias2)
{
    __shared__ __align__(16) __nv_bfloat16 sm[2][4][MATB]; // [buf][Ah,Al,Bh,Bl] 32KB
    const int tid = threadIdx.x;
    const int m0 = blockIdx.y * 128, n0 = blockIdx.x * 128;
    const int kb0 = blockIdx.z * kchunk;
    const int ke = min(K, kb0 + kchunk);
    C += (size_t)blockIdx.z * zstride;

    float acc[2][8][4];
#pragma unroll
    for (int i = 0; i < 2; i++)
#pragma unroll
        for (int j = 0; j < 8; j++)
#pragma unroll
            for (int q = 0; q < 4; q++) acc[i][j][q] = 0.f;

    const int ka = tid & 15, ra = tid >> 4;
    const int nn = tid & 127, k2 = tid >> 7;

    auto gload = [&](int kt, float* av, float* bv) {
#pragma unroll
        for (int i = 0; i < 8; i++) {
            int r = ra + 16 * i;
            int gm = m0 + r, gk = kt + ka;
            av[i] = (gm < M && gk < ke) ? A[(size_t)gm * lda + gk] : 0.f;
        }
        if (BT) {
#pragma unroll
            for (int i = 0; i < 8; i++) {
                int r = ra + 16 * i;
                int gn = n0 + r, gk = kt + ka;
                bv[i] = (gn < N && gk < ke) ? B[(size_t)gn * ldb + gk] : 0.f;
            }
        } else {
#pragma unroll
            for (int i = 0; i < 8; i++) {
                int kk = k2 + 2 * i;
                int gk = kt + kk, gn = n0 + nn;
                bv[i] = (gn < N && gk < ke) ? B[(size_t)gk * ldb + gn] : 0.f;
            }
        }
    };
    auto gstore = [&](int buf, const float* av, const float* bv) {
        char* a_hi = (char*)&sm[buf][0][0];
        char* a_lo = (char*)&sm[buf][1][0];
        char* b_hi = (char*)&sm[buf][2][0];
        char* b_lo = (char*)&sm[buf][3][0];
#pragma unroll
        for (int i = 0; i < 8; i++) {
            int r = ra + 16 * i;
            int o = swoff(r, ka);
            float v = av[i];
            __nv_bfloat16 hi = __float2bfloat16(v);
            *(__nv_bfloat16*)(a_hi + o) = hi;
            *(__nv_bfloat16*)(a_lo + o) = __float2bfloat16(v - __bfloat162float(hi));
        }
        if (BT) {
#pragma unroll
            for (int i = 0; i < 8; i++) {
                int r = ra + 16 * i;
                int o = swoff(r, ka);
                float v = bv[i];
                __nv_bfloat16 hi = __float2bfloat16(v);
                *(__nv_bfloat16*)(b_hi + o) = hi;
                *(__nv_bfloat16*)(b_lo + o) = __float2bfloat16(v - __bfloat162float(hi));
            }
        } else {
#pragma unroll
            for (int i = 0; i < 8; i++) {
                int kk = k2 + 2 * i;
                int o = swoff(nn, kk);
                float v = bv[i];
                __nv_bfloat16 hi = __float2bfloat16(v);
                *(__nv_bfloat16*)(b_hi + o) = hi;
                *(__nv_bfloat16*)(b_lo + o) = __float2bfloat16(v - __bfloat162float(hi));
            }
        }
    };

    const int lane = tid & 31, w = tid >> 5;
    const int wm = w & 3, wn = w >> 2;
    const int arow = wm * 32 + (lane & 15);
    const int akb = (lane >> 4) * 8;
    const int brow = wn * 64 + (lane & 7) + ((lane >> 4) << 3);
    const int bkb = ((lane >> 3) & 1) * 8;

    const int nk = (ke > kb0) ? (ke - kb0 + 15) / 16 : 0;
    float av[8], bv[8];
    if (nk > 0) {
        gload(kb0, av, bv);
        gstore(0, av, bv);
    }
    __syncthreads();

    for (int it = 0; it < nk; it++) {
        const int buf = it & 1;
        if (it + 1 < nk) gload(kb0 + 16 * (it + 1), av, bv);

        uint32_t a_hi = smem_u32(&sm[buf][0][0]);
        uint32_t a_lo = smem_u32(&sm[buf][1][0]);
        uint32_t b_hi = smem_u32(&sm[buf][2][0]);
        uint32_t b_lo = smem_u32(&sm[buf][3][0]);

        uint32_t ah[2][4], al[2][4], bh[8][2], bl[8][2];
#pragma unroll
        for (int ti = 0; ti < 2; ti++) {
            ldsm4(ah[ti][0], ah[ti][1], ah[ti][2], ah[ti][3],
                  a_hi + swoff(arow + 16 * ti, akb));
            ldsm4(al[ti][0], al[ti][1], al[ti][2], al[ti][3],
                  a_lo + swoff(arow + 16 * ti, akb));
        }
#pragma unroll
        for (int tp = 0; tp < 4; tp++) {
            uint32_t r0, r1, r2, r3;
            ldsm4(r0, r1, r2, r3, b_hi + swoff(brow + 16 * tp, bkb));
            bh[2 * tp][0] = r0; bh[2 * tp][1] = r1;
            bh[2 * tp + 1][0] = r2; bh[2 * tp + 1][1] = r3;
            ldsm4(r0, r1, r2, r3, b_lo + swoff(brow + 16 * tp, bkb));
            bl[2 * tp][0] = r0; bl[2 * tp][1] = r1;
            bl[2 * tp + 1][0] = r2; bl[2 * tp + 1][1] = r3;
        }
#pragma unroll
        for (int ti = 0; ti < 2; ti++)
#pragma unroll
            for (int tj = 0; tj < 8; tj++) {
                mma16816(acc[ti][tj], ah[ti][0], ah[ti][1], ah[ti][2], ah[ti][3],
                         bh[tj][0], bh[tj][1]);
                mma16816(acc[ti][tj], ah[ti][0], ah[ti][1], ah[ti][2], ah[ti][3],
                         bl[tj][0], bl[tj][1]);
                mma16816(acc[ti][tj], al[ti][0], al[ti][1], al[ti][2], al[ti][3],
                         bh[tj][0], bh[tj][1]);
            }
        if (it + 1 < nk) gstore(buf ^ 1, av, bv);
        __syncthreads();
    }

    const int erow = m0 + wm * 32 + (lane >> 2);
    const int ecol = n0 + wn * 64 + 2 * (lane & 3);
#pragma unroll
    for (int ti = 0; ti < 2; ti++)
#pragma unroll
        for (int tj = 0; tj < 8; tj++) {
            int m = erow + 16 * ti, n = ecol + 8 * tj;
#pragma unroll
            for (int q = 0; q < 4; q++) {
                int mm = m + (q >= 2 ? 8 : 0);
                int nnq = n + (q & 1);
                if (mm < M && nnq < N) {
                    float v = acc[ti][tj][q];
                    if (bias1) v += bias1[nnq];
                    if (bias2) v += bias2[nnq];
                    C[(size_t)mm * ldc + nnq] = v;
                }
            }
        }
}

// ---------------- emb0 + c0 (9 dot-rows vs embA, smem-staged) ----------------
__global__ __launch_bounds__(256)
void emb0_c0(const float* __restrict__ embA, const float* __restrict__ init_dec,
             const float* __restrict__ out_b, float* __restrict__ emb0,
             float* __restrict__ c0)
{
    __shared__ float sx[9][1024];
    const int tid = threadIdx.x, lane = tid & 31, w = tid >> 5;
    const int n = blockIdx.x * 8 + w;
    float acc[9];
#pragma unroll
    for (int r = 0; r < 9; r++) acc[r] = 0.f;
    for (int kb = 0; kb < Ee; kb += 1024) {
        int len = min(1024, Ee - kb);
        for (int idx = tid; idx < 9 * 1024; idx += 256) {
            int r = idx >> 10, c = idx & 1023;
            float v = 0.f;
            if (c < len) v = (r < 8) ? init_dec[(size_t)r * Ee + kb + c] : out_b[kb + c];
            sx[r][c] = v;
        }
        __syncthreads();
        const float* ar = embA + (size_t)n * ENZ + kb;
        for (int k = lane; k < len; k += 32) {
            float a = ar[k];
#pragma unroll
            for (int r = 0; r < 9; r++) acc[r] += a * sx[r][k];
        }
        __syncthreads();
    }
#pragma unroll
    for (int r = 0; r < 9; r++) acc[r] = wred(acc[r]);
    if (lane < 8) emb0[lane * Hh + n] = acc[lane];
    else if (lane == 8) c0[n] = acc[8];
}

// ---------------- encoder LSTM step ----------------
__global__ __launch_bounds__(256)
void enc_step(const float* __restrict__ Whh,
              const float* __restrict__ pre_t,
              const float* __restrict__ hp, const float* __restrict__ cp,
              float* __restrict__ hn, float* __restrict__ cn,
              float* __restrict__ eo)
{
    int w = (blockIdx.x * blockDim.x + threadIdx.x) >> 5;
    int lane = threadIdx.x & 31;
    if (w >= Hh) return;
    int h = w;
    float acc[4][8];
#pragma unroll
    for (int g = 0; g < 4; g++)
#pragma unroll
        for (int b = 0; b < 8; b++) acc[g][b] = 0.f;

    for (int k = lane; k < Hh; k += 32) {
        float hv[8];
#pragma unroll
        for (int b = 0; b < 8; b++) hv[b] = hp[b * Hh + k];
#pragma unroll
        for (int g = 0; g < 4; g++) {
            float wv = Whh[((size_t)(g * Hh + h)) * Hh + k];
#pragma unroll
            for (int b = 0; b < 8; b++) acc[g][b] += wv * hv[b];
        }
    }
#pragma unroll
    for (int g = 0; g < 4; g++)
#pragma unroll
        for (int b = 0; b < 8; b++) acc[g][b] = wred(acc[g][b]);

    if (lane < 8) {
        int b = lane;
        const float* pre = pre_t + (size_t)b * (Tt * G4H);
        float gi = pre[0 * Hh + h] + acc[0][b];
        float gf = pre[1 * Hh + h] + acc[1][b];
        float gg = pre[2 * Hh + h] + acc[2][b];
        float go = pre[3 * Hh + h] + acc[3][b];
        float iv = sg(gi), fv = sg(gf), gv = tanhf(gg), ov = sg(go);
        float c = fv * cp[b * Hh + h] + iv * gv;
        float hv = ov * tanhf(c);
        cn[b * Hh + h] = c;
        hn[b * Hh + h] = hv;
        eo[b * Hh + h] = hv;
    }
}

// ---------------- transpose eout [T,B,H] -> enc_t [B,H,T] ----------------
__global__ void transpose_enc(const float* __restrict__ eout, float* __restrict__ enc_t)
{
    __shared__ float tile[32][33];
    int b = blockIdx.z;
    int t0 = blockIdx.x * 32, h0 = blockIdx.y * 32;
    int tx = threadIdx.x, ty = threadIdx.y;  // 32 x 8
#pragma unroll
    for (int i = 0; i < 4; i++) {
        int t = t0 + ty + i * 8, h = h0 + tx;
        tile[ty + i * 8][tx] = (h < Hh) ? eout[((size_t)t * Bz + b) * Hh + h] : 0.f;
    }
    __syncthreads();
#pragma unroll
    for (int i = 0; i < 4; i++) {
        int h = h0 + ty + i * 8, t = t0 + tx;
        if (h < Hh) enc_t[((size_t)b * Hh + h) * Tt + t] = tile[tx][ty + i * 8];
    }
}

// ---------------- decoder: emb = h_prev @ M^T + c0 + noise-part ----------------
__global__ __launch_bounds__(256)
void dec_emb(const float* __restrict__ Mf, const float* __restrict__ c0,
             const float* __restrict__ n1s, const float* __restrict__ hp,
             float* __restrict__ emb)
{
    int w = (blockIdx.x * blockDim.x + threadIdx.x) >> 5;
    int lane = threadIdx.x & 31;
    if (w >= Hh) return;
    int h1 = w;
    float acc[8];
#pragma unroll
    for (int b = 0; b < 8; b++) acc[b] = 0.f;
    const float* mrow = Mf + (size_t)h1 * Hh;
    for (int k = lane; k < Hh; k += 32) {
        float mv = mrow[k];
#pragma unroll
        for (int b = 0; b < 8; b++) acc[b] += mv * hp[b * Hh + k];
    }
#pragma unroll
    for (int b = 0; b < 8; b++) acc[b] = wred(acc[b]);
    if (lane < 8) {
        int b = lane;
        emb[b * Hh + h1] = acc[b] + c0[h1] + n1s[b * Hh + h1];
    }
}

// ---------------- decoder: logits ----------------
__global__ __launch_bounds__(256)
void dec_logits(const float* __restrict__ attn_W, const float* __restrict__ emb,
                const float* __restrict__ hs, const float* __restrict__ pn2s,
                float* __restrict__ logits)
{
    int gw = (blockIdx.x * blockDim.x + threadIdx.x) >> 5;
    int lane = threadIdx.x & 31;
    if (gw >= Bz * Tt) return;
    int b = gw >> 7, t = gw & 127;
    const float* wr = attn_W + (size_t)t * (3 * Hh);
    const float* eb = emb + b * Hh;
    const float* hb = hs + b * Hh;
    float s = 0.f;
    for (int k = lane; k < Hh; k += 32)
        s += eb[k] * wr[k] + hb[k] * wr[Hh + k];
    s = wred(s);
    if (lane == 0) logits[b * Tt + t] = s + pn2s[b * Tt + t];
}

// ---------------- decoder: softmax + applied ----------------
__global__ __launch_bounds__(256)
void dec_applied(const float* __restrict__ logits, const float* __restrict__ enc_t,
                 float* __restrict__ app)
{
    int b = blockIdx.x, chunk = blockIdx.y;
    __shared__ float aw[Tt];
    int tid = threadIdx.x;
    if (tid < 32) {
        float v0 = logits[b * Tt + tid];
        float v1 = logits[b * Tt + 32 + tid];
        float v2 = logits[b * Tt + 64 + tid];
        float v3 = logits[b * Tt + 96 + tid];
        float mx = fmaxf(fmaxf(v0, v1), fmaxf(v2, v3));
#pragma unroll
        for (int o = 16; o; o >>= 1) mx = fmaxf(mx, __shfl_xor_sync(0xffffffffu, mx, o));
        float e0 = expf(v0 - mx), e1 = expf(v1 - mx), e2 = expf(v2 - mx), e3 = expf(v3 - mx);
        float s = wred(e0 + e1 + e2 + e3);
        float inv = 1.f / s;
        aw[tid] = e0 * inv; aw[tid + 32] = e1 * inv;
        aw[tid + 64] = e2 * inv; aw[tid + 96] = e3 * inv;
    }
    __syncthreads();
    int w = tid >> 5, lane = tid & 31;
    int hend = chunk * 125 + 125;
    for (int h = chunk * 125 + w; h < hend; h += 8) {
        const float* e = enc_t + ((size_t)b * Hh + h) * Tt;
        float s = 0.f;
#pragma unroll
        for (int t = lane; t < Tt; t += 32) s += aw[t] * e[t];
        s = wred(s);
        if (lane == 0) app[b * Hh + h] = s;
    }
}

// ---------------- decoder: combine + relu ----------------
__global__ __launch_bounds__(256)
void dec_comb(const float* __restrict__ W, const float* __restrict__ bias,
              const float* __restrict__ emb, const float* __restrict__ app,
              float* __restrict__ outv)
{
    int w = (blockIdx.x * blockDim.x + threadIdx.x) >> 5;
    int lane = threadIdx.x & 31;
    if (w >= Hh) return;
    int h1 = w;
    float acc[8];
#pragma unroll
    for (int b = 0; b < 8; b++) acc[b] = 0.f;
    const float* wrow = W + (size_t)h1 * (2 * Hh);
    for (int k = lane; k < 2 * Hh; k += 32) {
        float wv = wrow[k];
        const float* src = (k < Hh) ? emb : app;
        int kk = (k < Hh) ? k : k - Hh;
#pragma unroll
        for (int b = 0; b < 8; b++) acc[b] += wv * src[b * Hh + kk];
    }
#pragma unroll
    for (int b = 0; b < 8; b++) acc[b] = wred(acc[b]);
    if (lane < 8) {
        int b = lane;
        outv[b * Hh + h1] = fmaxf(acc[b] + bias[h1], 0.f);
    }
}

// ---------------- decoder LSTM step ----------------
__global__ __launch_bounds__(256)
void dec_lstm(const float* __restrict__ Wih, const float* __restrict__ Whh,
              const float* __restrict__ bih, const float* __restrict__ bhh,
              const float* __restrict__ x, const float* __restrict__ hp,
              const float* __restrict__ cp, float* __restrict__ hn,
              float* __restrict__ cn)
{
    int w = (blockIdx.x * blockDim.x + threadIdx.x) >> 5;
    int lane = threadIdx.x & 31;
    if (w >= Hh) return;
    int h = w;
    float acc[4][8];
#pragma unroll
    for (int g = 0; g < 4; g++)
#pragma unroll
        for (int b = 0; b < 8; b++) acc[g][b] = 0.f;

    for (int k = lane; k < Hh; k += 32) {
        float xv[8], hv[8];
#pragma unroll
        for (int b = 0; b < 8; b++) { xv[b] = x[b * Hh + k]; hv[b] = hp[b * Hh + k]; }
#pragma unroll
        for (int g = 0; g < 4; g++) {
            float wi = Wih[((size_t)(g * Hh + h)) * Hh + k];
            float wh = Whh[((size_t)(g * Hh + h)) * Hh + k];
#pragma unroll
            for (int b = 0; b < 8; b++) acc[g][b] += wi * xv[b] + wh * hv[b];
        }
    }
#pragma unroll
    for (int g = 0; g < 4; g++)
#pragma unroll
        for (int b = 0; b < 8; b++) acc[g][b] = wred(acc[g][b]);

    if (lane < 8) {
        int b = lane;
        float gi = acc[0][b] + bih[0 * Hh + h] + bhh[0 * Hh + h];
        float gf = acc[1][b] + bih[1 * Hh + h] + bhh[1 * Hh + h];
        float gg = acc[2][b] + bih[2 * Hh + h] + bhh[2 * Hh + h];
        float go = acc[3][b] + bih[3 * Hh + h] + bhh[3 * Hh + h];
        float iv = sg(gi), fv = sg(gf), gv = tanhf(gg), ov = sg(go);
        float c = fv * cp[b * Hh + h] + iv * gv;
        cn[b * Hh + h] = c;
        hn[b * Hh + h] = ov * tanhf(c);
    }
}

// ---------------- launcher ----------------
extern "C" void kernel_launch(void* const* d_in, const int* in_sizes, int n_in,
                              void* d_out, int out_size)
{
    int p = 0;
    const float* input    = (const float*)d_in[p++];
    if (in_sizes[p] == 1) p++;   // target_size scalar
    const float* noise1   = (const float*)d_in[p++];
    const float* noise2   = (const float*)d_in[p++];
    const float* init_dec = (const float*)d_in[p++];
    const float* enc_Wih  = (const float*)d_in[p++];
    const float* enc_Whh  = (const float*)d_in[p++];
    const float* enc_bih  = (const float*)d_in[p++];
    const float* enc_bhh  = (const float*)d_in[p++];
    const float* dec_Wih  = (const float*)d_in[p++];
    const float* dec_Whh  = (const float*)d_in[p++];
    const float* dec_bih  = (const float*)d_in[p++];
    const float* dec_bhh  = (const float*)d_in[p++];
    const float* emb_W    = (const float*)d_in[p++];
    const float* emb_b    = (const float*)d_in[p++];
    const float* attn_W   = (const float*)d_in[p++];
    const float* attn_b   = (const float*)d_in[p++];
    const float* comb_W   = (const float*)d_in[p++];
    const float* comb_b   = (const float*)d_in[p++];
    const float* out_W    = (const float*)d_in[p++];
    const float* out_b    = (const float*)d_in[p++];
    float* out = (float*)d_out;

    float* base = nullptr;
    cudaGetSymbolAddress((void**)&base, g_scratch);
    float* pre   = base + OFF_PRE;
    float* eout  = base + OFF_EOUT;
    float* enc_t = base + OFF_ENCT;
    float* hbuf  = base + OFF_HBUF;
    float* cbuf  = base + OFF_CBUF;
    float* Mf    = base + OFF_MF;
    float* c0    = base + OFF_C0;
    float* N1    = base + OFF_N1;
    float* emb0  = base + OFF_EMB0;
    float* hist  = base + OFF_HIST;
    float* cd    = base + OFF_CD;
    float* embb  = base + OFF_EMB;
    float* appb  = base + OFF_APP;
    float* cmbb  = base + OFF_CMB;
    float* PN2   = base + OFF_PN2;
    float* logi  = base + OFF_LOGI;
    float* partK = base + OFF_PARTK;

    // G1: pre-gates [B*T,4H] = input @ enc_Wih^T (+bih+bhh)
    gemm_bf16s<true><<<dim3(32, 8, 1), 256>>>(input, Ee, enc_Wih, Ee,
                                              pre, G4H, 0,
                                              Bz * Tt, G4H, Ee, Ee,
                                              enc_bih, enc_bhh);
    // G2 (split-K 8): Mf = embA @ out_W  [1000,1000]
    gemm_bf16s<false><<<dim3(8, 8, 8), 256>>>(emb_W, ENZ, out_W, Hh,
                                              partK, Hh, (size_t)Hh * Hh,
                                              Hh, Hh, Ee, 3824,
                                              nullptr, nullptr);
    reduceK<<<(Hh * Hh + 255) / 256, 256>>>(partK, (size_t)Hh * Hh, 8, Mf, Hh * Hh,
                                            nullptr, 1);
    // G3 (split-K 4): N1 = noise1 @ embNZ^T + emb_b  [512,1000]
    gemm_bf16s<true><<<dim3(8, 4, 4), 256>>>(noise1, NZ, emb_W + Ee, ENZ,
                                             partK, Hh, (size_t)Sz * Bz * Hh,
                                             Sz * Bz, Hh, NZ, 2512,
                                             nullptr, nullptr);
    reduceK<<<(Sz * Bz * Hh + 255) / 256, 256>>>(partK, (size_t)Sz * Bz * Hh, 4,
                                                 N1, Sz * Bz * Hh, emb_b, Hh);
    // PN2 = noise2 @ W3^T + attn_b  [512,128]
    gemm_bf16s<true><<<dim3(1, 4, 1), 256>>>(noise2, Hh, attn_W + 2 * Hh, 3 * Hh,
                                             PN2, Tt, 0,
                                             Sz * Bz, Tt, Hh, Hh,
                                             attn_b, nullptr);
    // emb0 + c0
    emb0_c0<<<125, 256>>>(emb_W, init_dec, out_b, emb0, c0);

    // zero initial encoder state
    zero_kernel<<<63, 256>>>(hbuf, 2 * Bz * Hh);
    zero_kernel<<<63, 256>>>(cbuf, 2 * Bz * Hh);

    // encoder recurrence
    for (int t = 0; t < Tt; t++) {
        const float* hp = hbuf + (t & 1) * (Bz * Hh);
        const float* cp = cbuf + (t & 1) * (Bz * Hh);
        float* hn = hbuf + ((t + 1) & 1) * (Bz * Hh);
        float* cn = cbuf + ((t + 1) & 1) * (Bz * Hh);
        enc_step<<<125, 256>>>(enc_Whh, pre + (size_t)t * G4H, hp, cp, hn, cn,
                               eout + (size_t)t * (Bz * Hh));
    }
    transpose_enc<<<dim3(4, 32, 8), dim3(32, 8)>>>(eout, enc_t);
    copy_kernel<<<32, 256>>>(hist, hbuf, Bz * Hh);
    copy_kernel<<<32, 256>>>(cd, cbuf, Bz * Hh);

    // decoder loop
    for (int s = 0; s < Sz; s++) {
        const float* hs = hist + (size_t)s * (Bz * Hh);
        float* hn = hist + (size_t)(s + 1) * (Bz * Hh);
        const float* cp = cd + (s & 1) * (Bz * Hh);
        float* cn = cd + ((s + 1) & 1) * (Bz * Hh);

        if (s == 0)
            add2_kernel<<<32, 256>>>(embb, emb0, N1, Bz * Hh);
        else
            dec_emb<<<125, 256>>>(Mf, c0, N1 + (size_t)s * (Bz * Hh), hs, embb);

        dec_logits<<<128, 256>>>(attn_W, embb, hs, PN2 + (size_t)s * (Bz * Tt), logi);
        dec_applied<<<dim3(8, 8), 256>>>(logi, enc_t, appb);
        dec_comb<<<125, 256>>>(comb_W, comb_b, embb, appb, cmbb);
        dec_lstm<<<125, 256>>>(dec_Wih, dec_Whh, dec_bih, dec_bhh,
                               cmbb, hs, cp, hn, cn);
    }

    // summary = hist[1..S] @ out_W^T + out_b  -> [512, 30522]
    gemm_bf16s<true><<<dim3(239, 4, 1), 256>>>(hist + Bz * Hh, Hh, out_W, Hh,
                                               out, Ee, 0,
                                               Sz * Bz, Ee, Hh, Hh,
                                               out_b, nullptr);
}

// round 11
// speedup vs baseline: 1.7359x; 1.3918x over previous
#include <cuda_runtime.h>
#include <cuda_bf16.h>
#include <cstdint>
#include <cstddef>

// Problem dims (fixed by the dataset)
#define Bz 8
#define Tt 128
#define Ee 30522
#define Hh 1000
#define Sz 64
#define NZ 10000
#define G4H 4000
#define ENZ (Ee + NZ)   // 40522
#define H4 250          // Hh / 4 (float4 per row)

// ---------------- scratch (static device memory; no allocation) ----------------
#define OFF_PRE    0UL             // [B*T, 4H]   4,096,000
#define OFF_EOUT   4096000UL       // [T,B,H]     1,024,000
#define OFF_ENCT   5120000UL       // [B,H,T]     1,024,000
#define OFF_HBUF   6144000UL       // 2x[B,H]     16,000
#define OFF_CBUF   6160000UL       // 2x[B,H]     16,000
#define OFF_MF     6176000UL       // [H,H]       1,000,000
#define OFF_C0     7176000UL       // [H]+pad     1,024
#define OFF_N1     7177024UL       // [S*B,H]     512,000
#define OFF_EMB0   7689024UL       // [B,H]       8,000
#define OFF_HIST   7697024UL       // [S+1,B,H]   520,000
#define OFF_CD     8217024UL       // 2x[B,H]     16,000
#define OFF_EMB    8233024UL       // [B,H]       8,000
#define OFF_APP    8241024UL       // [B,H]       8,000
#define OFF_CMB    8249024UL       // [B,H]       8,000
#define OFF_PN2    8257024UL       // [S*B,128]   65,536
#define OFF_LOGI   8322560UL       // [B,128]     1,024
#define OFF_PARTK  8323584UL       // split-K partials (8M floats)
#define SCRATCH_FLOATS 16323584UL

__device__ __align__(16) float g_scratch[SCRATCH_FLOATS];

// ---------------- helpers ----------------
__device__ __forceinline__ float wred(float v) {
#pragma unroll
    for (int o = 16; o; o >>= 1) v += __shfl_xor_sync(0xffffffffu, v, o);
    return v;
}
__device__ __forceinline__ float sg(float x) { return 1.f / (1.f + expf(-x)); }
__device__ __forceinline__ float dot4(float4 a, float4 b) {
    return a.x * b.x + a.y * b.y + a.z * b.z + a.w * b.w;
}
__device__ __forceinline__ float4 f4z() { return make_float4(0.f, 0.f, 0.f, 0.f); }

__device__ __forceinline__ uint32_t smem_u32(const void* p) {
    uint32_t r;
    asm("{ .reg .u64 t; cvta.to.shared.u64 t, %1; cvt.u32.u64 %0, t; }"
        : "=r"(r) : "l"(p));
    return r;
}
__device__ __forceinline__ void ldsm4(uint32_t& r0, uint32_t& r1, uint32_t& r2, uint32_t& r3,
                                      uint32_t addr) {
    asm volatile("ldmatrix.sync.aligned.m8n8.x4.shared.b16 {%0,%1,%2,%3}, [%4];"
                 : "=r"(r0), "=r"(r1), "=r"(r2), "=r"(r3) : "r"(addr));
}
__device__ __forceinline__ void mma16816(float* c, uint32_t a0, uint32_t a1, uint32_t a2,
                                         uint32_t a3, uint32_t b0, uint32_t b1) {
    asm volatile(
        "mma.sync.aligned.m16n8k16.row.col.f32.bf16.bf16.f32 "
        "{%0,%1,%2,%3},{%4,%5,%6,%7},{%8,%9},{%0,%1,%2,%3};"
        : "+f"(c[0]), "+f"(c[1]), "+f"(c[2]), "+f"(c[3])
        : "r"(a0), "r"(a1), "r"(a2), "r"(a3), "r"(b0), "r"(b1));
}

__global__ void zero_kernel(float* p, int n) {
    int i = blockIdx.x * blockDim.x + threadIdx.x;
    if (i < n) p[i] = 0.f;
}
__global__ void copy_kernel(float* dst, const float* src, int n) {
    int i = blockIdx.x * blockDim.x + threadIdx.x;
    if (i < n) dst[i] = src[i];
}
__global__ void add2_kernel(float* dst, const float* a, const float* b, int n) {
    int i = blockIdx.x * blockDim.x + threadIdx.x;
    if (i < n) dst[i] = a[i] + b[i];
}
__global__ void reduceK(const float* __restrict__ part, size_t zstride, int nz,
                        float* __restrict__ C, int n,
                        const float* __restrict__ bias, int ncols) {
    int i = blockIdx.x * blockDim.x + threadIdx.x;
    if (i >= n) return;
    float s = 0.f;
    for (int z = 0; z < nz; z++) s += part[(size_t)z * zstride + i];
    if (bias) s += bias[i % ncols];
    C[i] = s;
}

// ---------------- split-bf16 tensor-core GEMM (unchanged from R8) ----------------
#define MATB (128 * 16)  // bf16 elements per matrix buffer (4KB)

__device__ __forceinline__ int swoff(int r, int e) {
    return r * 32 + ((((e >> 3) ^ (r >> 2)) & 1) << 4) + (e & 7) * 2;
}

template <bool BT>
__global__ __launch_bounds__(256, 2)
void gemm_bf16s(const float* __restrict__ A, long lda,
                const float* __restrict__ B, long ldb,
                float* __restrict__ C, long ldc, size_t zstride,
                int M, int N, int K, int kchunk,
                const float* __restrict__ bias1, const float* __restrict__ bias2)
{
    __shared__ __align__(16) __nv_bfloat16 sm[2][4][MATB]; // [buf][Ah,Al,Bh,Bl] 32KB
    const int tid = threadIdx.x;
    const int m0 = blockIdx.y * 128, n0 = blockIdx.x * 128;
    const int kb0 = blockIdx.z * kchunk;
    const int ke = min(K, kb0 + kchunk);
    C += (size_t)blockIdx.z * zstride;

    float acc[2][8][4];
#pragma unroll
    for (int i = 0; i < 2; i++)
#pragma unroll
        for (int j = 0; j < 8; j++)
#pragma unroll
            for (int q = 0; q < 4; q++) acc[i][j][q] = 0.f;

    const int ka = tid & 15, ra = tid >> 4;
    const int nn = tid & 127, k2 = tid >> 7;

    auto gload = [&](int kt, float* av, float* bv) {
#pragma unroll
        for (int i = 0; i < 8; i++) {
            int r = ra + 16 * i;
            int gm = m0 + r, gk = kt + ka;
            av[i] = (gm < M && gk < ke) ? A[(size_t)gm * lda + gk] : 0.f;
        }
        if (BT) {
#pragma unroll
            for (int i = 0; i < 8; i++) {
                int r = ra + 16 * i;
                int gn = n0 + r, gk = kt + ka;
                bv[i] = (gn < N && gk < ke) ? B[(size_t)gn * ldb + gk] : 0.f;
            }
        } else {
#pragma unroll
            for (int i = 0; i < 8; i++) {
                int kk = k2 + 2 * i;
                int gk = kt + kk, gn = n0 + nn;
                bv[i] = (gn < N && gk < ke) ? B[(size_t)gk * ldb + gn] : 0.f;
            }
        }
    };
    auto gstore = [&](int buf, const float* av, const float* bv) {
        char* a_hi = (char*)&sm[buf][0][0];
        char* a_lo = (char*)&sm[buf][1][0];
        char* b_hi = (char*)&sm[buf][2][0];
        char* b_lo = (char*)&sm[buf][3][0];
#pragma unroll
        for (int i = 0; i < 8; i++) {
            int r = ra + 16 * i;
            int o = swoff(r, ka);
            float v = av[i];
            __nv_bfloat16 hi = __float2bfloat16(v);
            *(__nv_bfloat16*)(a_hi + o) = hi;
            *(__nv_bfloat16*)(a_lo + o) = __float2bfloat16(v - __bfloat162float(hi));
        }
        if (BT) {
#pragma unroll
            for (int i = 0; i < 8; i++) {
                int r = ra + 16 * i;
                int o = swoff(r, ka);
                float v = bv[i];
                __nv_bfloat16 hi = __float2bfloat16(v);
                *(__nv_bfloat16*)(b_hi + o) = hi;
                *(__nv_bfloat16*)(b_lo + o) = __float2bfloat16(v - __bfloat162float(hi));
            }
        } else {
#pragma unroll
            for (int i = 0; i < 8; i++) {
                int kk = k2 + 2 * i;
                int o = swoff(nn, kk);
                float v = bv[i];
                __nv_bfloat16 hi = __float2bfloat16(v);
                *(__nv_bfloat16*)(b_hi + o) = hi;
                *(__nv_bfloat16*)(b_lo + o) = __float2bfloat16(v - __bfloat162float(hi));
            }
        }
    };

    const int lane = tid & 31, w = tid >> 5;
    const int wm = w & 3, wn = w >> 2;
    const int arow = wm * 32 + (lane & 15);
    const int akb = (lane >> 4) * 8;
    const int brow = wn * 64 + (lane & 7) + ((lane >> 4) << 3);
    const int bkb = ((lane >> 3) & 1) * 8;

    const int nk = (ke > kb0) ? (ke - kb0 + 15) / 16 : 0;
    float av[8], bv[8];
    if (nk > 0) {
        gload(kb0, av, bv);
        gstore(0, av, bv);
    }
    __syncthreads();

    for (int it = 0; it < nk; it++) {
        const int buf = it & 1;
        if (it + 1 < nk) gload(kb0 + 16 * (it + 1), av, bv);

        uint32_t a_hi = smem_u32(&sm[buf][0][0]);
        uint32_t a_lo = smem_u32(&sm[buf][1][0]);
        uint32_t b_hi = smem_u32(&sm[buf][2][0]);
        uint32_t b_lo = smem_u32(&sm[buf][3][0]);

        uint32_t ah[2][4], al[2][4], bh[8][2], bl[8][2];
#pragma unroll
        for (int ti = 0; ti < 2; ti++) {
            ldsm4(ah[ti][0], ah[ti][1], ah[ti][2], ah[ti][3],
                  a_hi + swoff(arow + 16 * ti, akb));
            ldsm4(al[ti][0], al[ti][1], al[ti][2], al[ti][3],
                  a_lo + swoff(arow + 16 * ti, akb));
        }
#pragma unroll
        for (int tp = 0; tp < 4; tp++) {
            uint32_t r0, r1, r2, r3;
            ldsm4(r0, r1, r2, r3, b_hi + swoff(brow + 16 * tp, bkb));
            bh[2 * tp][0] = r0; bh[2 * tp][1] = r1;
            bh[2 * tp + 1][0] = r2; bh[2 * tp + 1][1] = r3;
            ldsm4(r0, r1, r2, r3, b_lo + swoff(brow + 16 * tp, bkb));
            bl[2 * tp][0] = r0; bl[2 * tp][1] = r1;
            bl[2 * tp + 1][0] = r2; bl[2 * tp + 1][1] = r3;
        }
#pragma unroll
        for (int ti = 0; ti < 2; ti++)
#pragma unroll
            for (int tj = 0; tj < 8; tj++) {
                mma16816(acc[ti][tj], ah[ti][0], ah[ti][1], ah[ti][2], ah[ti][3],
                         bh[tj][0], bh[tj][1]);
                mma16816(acc[ti][tj], ah[ti][0], ah[ti][1], ah[ti][2], ah[ti][3],
                         bl[tj][0], bl[tj][1]);
                mma16816(acc[ti][tj], al[ti][0], al[ti][1], al[ti][2], al[ti][3],
                         bh[tj][0], bh[tj][1]);
            }
        if (it + 1 < nk) gstore(buf ^ 1, av, bv);
        __syncthreads();
    }

    const int erow = m0 + wm * 32 + (lane >> 2);
    const int ecol = n0 + wn * 64 + 2 * (lane & 3);
#pragma unroll
    for (int ti = 0; ti < 2; ti++)
#pragma unroll
        for (int tj = 0; tj < 8; tj++) {
            int m = erow + 16 * ti, n = ecol + 8 * tj;
#pragma unroll
            for (int q = 0; q < 4; q++) {
                int mm = m + (q >= 2 ? 8 : 0);
                int nnq = n + (q & 1);
                if (mm < M && nnq < N) {
                    float v = acc[ti][tj][q];
                    if (bias1) v += bias1[nnq];
                    if (bias2) v += bias2[nnq];
                    C[(size_t)mm * ldc + nnq] = v;
                }
            }
        }
}

// ---------------- emb0 + c0 (9 dot-rows vs embA, smem-staged) ----------------
__global__ __launch_bounds__(256)
void emb0_c0(const float* __restrict__ embA, const float* __restrict__ init_dec,
             const float* __restrict__ out_b, float* __restrict__ emb0,
             float* __restrict__ c0)
{
    __shared__ float sx[9][1024];
    const int tid = threadIdx.x, lane = tid & 31, w = tid >> 5;
    const int n = blockIdx.x * 8 + w;
    float acc[9];
#pragma unroll
    for (int r = 0; r < 9; r++) acc[r] = 0.f;
    for (int kb = 0; kb < Ee; kb += 1024) {
        int len = min(1024, Ee - kb);
        for (int idx = tid; idx < 9 * 1024; idx += 256) {
            int r = idx >> 10, c = idx & 1023;
            float v = 0.f;
            if (c < len) v = (r < 8) ? init_dec[(size_t)r * Ee + kb + c] : out_b[kb + c];
            sx[r][c] = v;
        }
        __syncthreads();
        const float* ar = embA + (size_t)n * ENZ + kb;
        for (int k = lane; k < len; k += 32) {
            float a = ar[k];
#pragma unroll
            for (int r = 0; r < 9; r++) acc[r] += a * sx[r][k];
        }
        __syncthreads();
    }
#pragma unroll
    for (int r = 0; r < 9; r++) acc[r] = wred(acc[r]);
    if (lane < 8) emb0[lane * Hh + n] = acc[lane];
    else if (lane == 8) c0[n] = acc[8];
}

// ---------------- encoder LSTM step (float4, fully unrolled) ----------------
__global__ __launch_bounds__(256)
void enc_step(const float* __restrict__ Whh,
              const float* __restrict__ pre_t,
              const float* __restrict__ hp, const float* __restrict__ cp,
              float* __restrict__ hn, float* __restrict__ cn,
              float* __restrict__ eo)
{
    int w = (blockIdx.x * blockDim.x + threadIdx.x) >> 5;
    int lane = threadIdx.x & 31;
    if (w >= Hh) return;
    const int h = w;
    const float4* W4 = (const float4*)Whh;
    const float4* hp4 = (const float4*)hp;

    float acc[4][8];
#pragma unroll
    for (int g = 0; g < 4; g++)
#pragma unroll
        for (int b = 0; b < 8; b++) acc[g][b] = 0.f;

#pragma unroll
    for (int i = 0; i < 8; i++) {
        int k4 = lane + 32 * i;
        bool ok = (k4 < H4);
        float4 hv[8];
#pragma unroll
        for (int b = 0; b < 8; b++) hv[b] = ok ? hp4[b * H4 + k4] : f4z();
#pragma unroll
        for (int g = 0; g < 4; g++) {
            float4 wv = ok ? W4[(size_t)(g * Hh + h) * H4 + k4] : f4z();
#pragma unroll
            for (int b = 0; b < 8; b++) acc[g][b] += dot4(wv, hv[b]);
        }
    }
#pragma unroll
    for (int g = 0; g < 4; g++)
#pragma unroll
        for (int b = 0; b < 8; b++) acc[g][b] = wred(acc[g][b]);

    if (lane < 8) {
        int b = lane;
        const float* pre = pre_t + (size_t)b * (Tt * G4H);
        float gi = pre[0 * Hh + h] + acc[0][b];
        float gf = pre[1 * Hh + h] + acc[1][b];
        float gg = pre[2 * Hh + h] + acc[2][b];
        float go = pre[3 * Hh + h] + acc[3][b];
        float iv = sg(gi), fv = sg(gf), gv = tanhf(gg), ov = sg(go);
        float c = fv * cp[b * Hh + h] + iv * gv;
        float hv = ov * tanhf(c);
        cn[b * Hh + h] = c;
        hn[b * Hh + h] = hv;
        eo[b * Hh + h] = hv;
    }
}

// ---------------- transpose eout [T,B,H] -> enc_t [B,H,T] ----------------
__global__ void transpose_enc(const float* __restrict__ eout, float* __restrict__ enc_t)
{
    __shared__ float tile[32][33];
    int b = blockIdx.z;
    int t0 = blockIdx.x * 32, h0 = blockIdx.y * 32;
    int tx = threadIdx.x, ty = threadIdx.y;  // 32 x 8
#pragma unroll
    for (int i = 0; i < 4; i++) {
        int t = t0 + ty + i * 8, h = h0 + tx;
        tile[ty + i * 8][tx] = (h < Hh) ? eout[((size_t)t * Bz + b) * Hh + h] : 0.f;
    }
    __syncthreads();
#pragma unroll
    for (int i = 0; i < 4; i++) {
        int h = h0 + ty + i * 8, t = t0 + tx;
        if (h < Hh) enc_t[((size_t)b * Hh + h) * Tt + t] = tile[tx][ty + i * 8];
    }
}

// ---------------- decoder: emb = h_prev @ M^T + c0 + noise-part (float4) --------
__global__ __launch_bounds__(256)
void dec_emb(const float* __restrict__ Mf, const float* __restrict__ c0,
             const float* __restrict__ n1s, const float* __restrict__ hp,
             float* __restrict__ emb)
{
    int w = (blockIdx.x * blockDim.x + threadIdx.x) >> 5;
    int lane = threadIdx.x & 31;
    if (w >= Hh) return;
    const int h1 = w;
    const float4* M4 = (const float4*)(Mf + (size_t)h1 * Hh);
    const float4* hp4 = (const float4*)hp;

    float acc[8];
#pragma unroll
    for (int b = 0; b < 8; b++) acc[b] = 0.f;

#pragma unroll
    for (int i = 0; i < 8; i++) {
        int k4 = lane + 32 * i;
        bool ok = (k4 < H4);
        float4 mv = ok ? M4[k4] : f4z();
#pragma unroll
        for (int b = 0; b < 8; b++) {
            float4 hv = ok ? hp4[b * H4 + k4] : f4z();
            acc[b] += dot4(mv, hv);
        }
    }
#pragma unroll
    for (int b = 0; b < 8; b++) acc[b] = wred(acc[b]);
    if (lane < 8) {
        int b = lane;
        emb[b * Hh + h1] = acc[b] + c0[h1] + n1s[b * Hh + h1];
    }
}

// ---------------- decoder: logits (float4) ----------------
__global__ __launch_bounds__(256)
void dec_logits(const float* __restrict__ attn_W, const float* __restrict__ emb,
                const float* __restrict__ hs, const float* __restrict__ pn2s,
                float* __restrict__ logits)
{
    int gw = (blockIdx.x * blockDim.x + threadIdx.x) >> 5;
    int lane = threadIdx.x & 31;
    if (gw >= Bz * Tt) return;
    int b = gw >> 7, t = gw & 127;
    const float4* wr4 = (const float4*)(attn_W + (size_t)t * (3 * Hh));
    const float4* e4 = (const float4*)(emb + b * Hh);
    const float4* h4 = (const float4*)(hs + b * Hh);
    float s = 0.f;
#pragma unroll
    for (int i = 0; i < 8; i++) {
        int k4 = lane + 32 * i;
        if (k4 < H4) s += dot4(e4[k4], wr4[k4]);
    }
#pragma unroll
    for (int i = 0; i < 8; i++) {
        int k4 = lane + 32 * i;
        if (k4 < H4) s += dot4(h4[k4], wr4[H4 + k4]);
    }
    s = wred(s);
    if (lane == 0) logits[b * Tt + t] = s + pn2s[b * Tt + t];
}

// ---------------- decoder: softmax + applied (float4 row dots) ----------------
__global__ __launch_bounds__(256)
void dec_applied(const float* __restrict__ logits, const float* __restrict__ enc_t,
                 float* __restrict__ app)
{
    int b = blockIdx.x, chunk = blockIdx.y;
    __shared__ __align__(16) float aw[Tt];
    int tid = threadIdx.x;
    if (tid < 32) {
        float v0 = logits[b * Tt + tid];
        float v1 = logits[b * Tt + 32 + tid];
        float v2 = logits[b * Tt + 64 + tid];
        float v3 = logits[b * Tt + 96 + tid];
        float mx = fmaxf(fmaxf(v0, v1), fmaxf(v2, v3));
#pragma unroll
        for (int o = 16; o; o >>= 1) mx = fmaxf(mx, __shfl_xor_sync(0xffffffffu, mx, o));
        float e0 = expf(v0 - mx), e1 = expf(v1 - mx), e2 = expf(v2 - mx), e3 = expf(v3 - mx);
        float s = wred(e0 + e1 + e2 + e3);
        float inv = 1.f / s;
        aw[tid] = e0 * inv; aw[tid + 32] = e1 * inv;
        aw[tid + 64] = e2 * inv; aw[tid + 96] = e3 * inv;
    }
    __syncthreads();
    int w = tid >> 5, lane = tid & 31;
    float4 awv = ((const float4*)aw)[lane];   // t = 4*lane .. 4*lane+3
    int hbeg = chunk * 125;
#pragma unroll
    for (int it = 0; it < 16; it++) {
        int h = hbeg + w + it * 8;
        if (h < hbeg + 125) {
            const float4* e4 = (const float4*)(enc_t + ((size_t)b * Hh + h) * Tt);
            float sd = dot4(awv, e4[lane]);
            sd = wred(sd);
            if (lane == 0) app[b * Hh + h] = sd;
        }
    }
}

// ---------------- decoder: combine + relu (float4) ----------------
__global__ __launch_bounds__(256)
void dec_comb(const float* __restrict__ W, const float* __restrict__ bias,
              const float* __restrict__ emb, const float* __restrict__ app,
              float* __restrict__ outv)
{
    int w = (blockIdx.x * blockDim.x + threadIdx.x) >> 5;
    int lane = threadIdx.x & 31;
    if (w >= Hh) return;
    const int h1 = w;
    const float4* W4 = (const float4*)(W + (size_t)h1 * (2 * Hh));
    const float4* e4 = (const float4*)emb;
    const float4* a4 = (const float4*)app;

    float acc[8];
#pragma unroll
    for (int b = 0; b < 8; b++) acc[b] = 0.f;

#pragma unroll
    for (int i = 0; i < 8; i++) {
        int k4 = lane + 32 * i;
        bool ok = (k4 < H4);
        float4 wv = ok ? W4[k4] : f4z();
#pragma unroll
        for (int b = 0; b < 8; b++) {
            float4 v = ok ? e4[b * H4 + k4] : f4z();
            acc[b] += dot4(wv, v);
        }
    }
#pragma unroll
    for (int i = 0; i < 8; i++) {
        int k4 = lane + 32 * i;
        bool ok = (k4 < H4);
        float4 wv = ok ? W4[H4 + k4] : f4z();
#pragma unroll
        for (int b = 0; b < 8; b++) {
            float4 v = ok ? a4[b * H4 + k4] : f4z();
            acc[b] += dot4(wv, v);
        }
    }
#pragma unroll
    for (int b = 0; b < 8; b++) acc[b] = wred(acc[b]);
    if (lane < 8) {
        int b = lane;
        outv[b * Hh + h1] = fmaxf(acc[b] + bias[h1], 0.f);
    }
}

// ---------------- decoder LSTM step (float4) ----------------
__global__ __launch_bounds__(256)
void dec_lstm(const float* __restrict__ Wih, const float* __restrict__ Whh,
              const float* __restrict__ bih, const float* __restrict__ bhh,
              const float* __restrict__ x, const float* __restrict__ hp,
              const float* __restrict__ cp, float* __restrict__ hn,
              float* __restrict__ cn)
{
    int w = (blockIdx.x * blockDim.x + threadIdx.x) >> 5;
    int lane = threadIdx.x & 31;
    if (w >= Hh) return;
    const int h = w;
    const float4* Wi4 = (const float4*)Wih;
    const float4* Wh4 = (const float4*)Whh;
    const float4* x4 = (const float4*)x;
    const float4* hp4 = (const float4*)hp;

    float acc[4][8];
#pragma unroll
    for (int g = 0; g < 4; g++)
#pragma unroll
        for (int b = 0; b < 8; b++) acc[g][b] = 0.f;

#pragma unroll
    for (int i = 0; i < 8; i++) {
        int k4 = lane + 32 * i;
        bool ok = (k4 < H4);
        float4 xv[8], hv[8];
#pragma unroll
        for (int b = 0; b < 8; b++) {
            xv[b] = ok ? x4[b * H4 + k4] : f4z();
            hv[b] = ok ? hp4[b * H4 + k4] : f4z();
        }
#pragma unroll
        for (int g = 0; g < 4; g++) {
            float4 wi = ok ? Wi4[(size_t)(g * Hh + h) * H4 + k4] : f4z();
            float4 wh = ok ? Wh4[(size_t)(g * Hh + h) * H4 + k4] : f4z();
#pragma unroll
            for (int b = 0; b < 8; b++)
                acc[g][b] += dot4(wi, xv[b]) + dot4(wh, hv[b]);
        }
    }
#pragma unroll
    for (int g = 0; g < 4; g++)
#pragma unroll
        for (int b = 0; b < 8; b++) acc[g][b] = wred(acc[g][b]);

    if (lane < 8) {
        int b = lane;
        float gi = acc[0][b] + bih[0 * Hh + h] + bhh[0 * Hh + h];
        float gf = acc[1][b] + bih[1 * Hh + h] + bhh[1 * Hh + h];
        float gg = acc[2][b] + bih[2 * Hh + h] + bhh[2 * Hh + h];
        float go = acc[3][b] + bih[3 * Hh + h] + bhh[3 * Hh + h];
        float iv = sg(gi), fv = sg(gf), gv = tanhf(gg), ov = sg(go);
        float c = fv * cp[b * Hh + h] + iv * gv;
        cn[b * Hh + h] = c;
        hn[b * Hh + h] = ov * tanhf(c);
    }
}

// ---------------- launcher ----------------
extern "C" void kernel_launch(void* const* d_in, const int* in_sizes, int n_in,
                              void* d_out, int out_size)
{
    int p = 0;
    const float* input    = (const float*)d_in[p++];
    if (in_sizes[p] == 1) p++;   // target_size scalar
    const float* noise1   = (const float*)d_in[p++];
    const float* noise2   = (const float*)d_in[p++];
    const float* init_dec = (const float*)d_in[p++];
    const float* enc_Wih  = (const float*)d_in[p++];
    const float* enc_Whh  = (const float*)d_in[p++];
    const float* enc_bih  = (const float*)d_in[p++];
    const float* enc_bhh  = (const float*)d_in[p++];
    const float* dec_Wih  = (const float*)d_in[p++];
    const float* dec_Whh  = (const float*)d_in[p++];
    const float* dec_bih  = (const float*)d_in[p++];
    const float* dec_bhh  = (const float*)d_in[p++];
    const float* emb_W    = (const float*)d_in[p++];
    const float* emb_b    = (const float*)d_in[p++];
    const float* attn_W   = (const float*)d_in[p++];
    const float* attn_b   = (const float*)d_in[p++];
    const float* comb_W   = (const float*)d_in[p++];
    const float* comb_b   = (const float*)d_in[p++];
    const float* out_W    = (const float*)d_in[p++];
    const float* out_b    = (const float*)d_in[p++];
    float* out = (float*)d_out;

    float* base = nullptr;
    cudaGetSymbolAddress((void**)&base, g_scratch);
    float* pre   = base + OFF_PRE;
    float* eout  = base + OFF_EOUT;
    float* enc_t = base + OFF_ENCT;
    float* hbuf  = base + OFF_HBUF;
    float* cbuf  = base + OFF_CBUF;
    float* Mf    = base + OFF_MF;
    float* c0    = base + OFF_C0;
    float* N1    = base + OFF_N1;
    float* emb0  = base + OFF_EMB0;
    float* hist  = base + OFF_HIST;
    float* cd    = base + OFF_CD;
    float* embb  = base + OFF_EMB;
    float* appb  = base + OFF_APP;
    float* cmbb  = base + OFF_CMB;
    float* PN2   = base + OFF_PN2;
    float* logi  = base + OFF_LOGI;
    float* partK = base + OFF_PARTK;

    // G1: pre-gates [B*T,4H] = input @ enc_Wih^T (+bih+bhh)
    gemm_bf16s<true><<<dim3(32, 8, 1), 256>>>(input, Ee, enc_Wih, Ee,
                                              pre, G4H, 0,
                                              Bz * Tt, G4H, Ee, Ee,
                                              enc_bih, enc_bhh);
    // G2 (split-K 8): Mf = embA @ out_W  [1000,1000]
    gemm_bf16s<false><<<dim3(8, 8, 8), 256>>>(emb_W, ENZ, out_W, Hh,
                                              partK, Hh, (size_t)Hh * Hh,
                                              Hh, Hh, Ee, 3824,
                                              nullptr, nullptr);
    reduceK<<<(Hh * Hh + 255) / 256, 256>>>(partK, (size_t)Hh * Hh, 8, Mf, Hh * Hh,
                                            nullptr, 1);
    // G3 (split-K 4): N1 = noise1 @ embNZ^T + emb_b  [512,1000]
    gemm_bf16s<true><<<dim3(8, 4, 4), 256>>>(noise1, NZ, emb_W + Ee, ENZ,
                                             partK, Hh, (size_t)Sz * Bz * Hh,
                                             Sz * Bz, Hh, NZ, 2512,
                                             nullptr, nullptr);
    reduceK<<<(Sz * Bz * Hh + 255) / 256, 256>>>(partK, (size_t)Sz * Bz * Hh, 4,
                                                 N1, Sz * Bz * Hh, emb_b, Hh);
    // PN2 = noise2 @ W3^T + attn_b  [512,128]
    gemm_bf16s<true><<<dim3(1, 4, 1), 256>>>(noise2, Hh, attn_W + 2 * Hh, 3 * Hh,
                                             PN2, Tt, 0,
                                             Sz * Bz, Tt, Hh, Hh,
                                             attn_b, nullptr);
    // emb0 + c0
    emb0_c0<<<125, 256>>>(emb_W, init_dec, out_b, emb0, c0);

    // zero initial encoder state
    zero_kernel<<<63, 256>>>(hbuf, 2 * Bz * Hh);
    zero_kernel<<<63, 256>>>(cbuf, 2 * Bz * Hh);

    // encoder recurrence
    for (int t = 0; t < Tt; t++) {
        const float* hp = hbuf + (t & 1) * (Bz * Hh);
        const float* cp = cbuf + (t & 1) * (Bz * Hh);
        float* hn = hbuf + ((t + 1) & 1) * (Bz * Hh);
        float* cn = cbuf + ((t + 1) & 1) * (Bz * Hh);
        enc_step<<<125, 256>>>(enc_Whh, pre + (size_t)t * G4H, hp, cp, hn, cn,
                               eout + (size_t)t * (Bz * Hh));
    }
    transpose_enc<<<dim3(4, 32, 8), dim3(32, 8)>>>(eout, enc_t);
    copy_kernel<<<32, 256>>>(hist, hbuf, Bz * Hh);
    copy_kernel<<<32, 256>>>(cd, cbuf, Bz * Hh);

    // decoder loop
    for (int s = 0; s < Sz; s++) {
        const float* hs = hist + (size_t)s * (Bz * Hh);
        float* hn = hist + (size_t)(s + 1) * (Bz * Hh);
        const float* cp = cd + (s & 1) * (Bz * Hh);
        float* cn = cd + ((s + 1) & 1) * (Bz * Hh);

        if (s == 0)
            add2_kernel<<<32, 256>>>(embb, emb0, N1, Bz * Hh);
        else
            dec_emb<<<125, 256>>>(Mf, c0, N1 + (size_t)s * (Bz * Hh), hs, embb);

        dec_logits<<<128, 256>>>(attn_W, embb, hs, PN2 + (size_t)s * (Bz * Tt), logi);
        dec_applied<<<dim3(8, 8), 256>>>(logi, enc_t, appb);
        dec_comb<<<125, 256>>>(comb_W, comb_b, embb, appb, cmbb);
        dec_lstm<<<125, 256>>>(dec_Wih, dec_Whh, dec_bih, dec_bhh,
                               cmbb, hs, cp, hn, cn);
    }

    // summary = hist[1..S] @ out_W^T + out_b  -> [512, 30522]
    gemm_bf16s<true><<<dim3(239, 4, 1), 256>>>(hist + Bz * Hh, Hh, out_W, Hh,
                                               out, Ee, 0,
                                               Sz * Bz, Ee, Hh, Hh,
                                               out_b, nullptr);
}